// round 10
// baseline (speedup 1.0000x reference)
#include <cuda_runtime.h>
#include <cuda_fp16.h>
#include <math.h>
#include <stdint.h>

#define NB     64
#define SHIFT  150
#define LEN    200
#define NH     128
#define MTILE  128
#define NTHR   512
#define NCHUNK 8
#define EPSF   1e-7f
#define HALF_INV_LN10 0.21714724095162588f

#define FP     200                 // frame pitch (halfs); rows -> banks 4r mod 32
#define BP     56                  // B pitch (halfs); rows -> banks 28r mod 32, 112B = 16B-mult
#define KC     48                  // K per chunk (3 k16 steps); 48*4 + 16 = 208
#define NCHK   5
#define BCH    28672               // bytes per B half-split chunk: 256*56*2

// smem layout (bytes)
#define SM_FH   0                  // frames hi [128][200] half = 51200
#define SM_FL   51200
#define SM_B0H  102400             // double-buffered B: hi/lo per buffer
#define SM_B0L  131072
#define SM_B1H  159744
#define SM_B1L  188416
#define SMEM_TOTAL 217088

// epilogue overlay (pitch 132 floats)
#define OFF_V    0
#define OFF_IM   67584
#define OFF_MEAN 135168
#define OFF_INV  135680

__device__ float g_mu[NB];
__device__ float g_sd[NB];
__device__ float g_psum[NB * NCHUNK];
__device__ float g_psq [NB * NCHUNK];
__device__ __align__(16) __half g_bh[NCHK * 256 * BP];
__device__ __align__(16) __half g_bl[NCHK * 256 * BP];

__device__ __forceinline__ void mma16(float* d, const uint32_t* a, const uint32_t* bf) {
    asm volatile("mma.sync.aligned.m16n8k16.row.col.f32.f16.f16.f32 "
        "{%0,%1,%2,%3}, {%4,%5,%6,%7}, {%8,%9}, {%0,%1,%2,%3};"
        : "+f"(d[0]), "+f"(d[1]), "+f"(d[2]), "+f"(d[3])
        : "r"(a[0]), "r"(a[1]), "r"(a[2]), "r"(a[3]), "r"(bf[0]), "r"(bf[1]));
}
__device__ __forceinline__ void ldsm4(uint32_t* r, uint32_t addr) {
    asm volatile("ldmatrix.sync.aligned.m8n8.x4.shared.b16 {%0,%1,%2,%3}, [%4];"
        : "=r"(r[0]), "=r"(r[1]), "=r"(r[2]), "=r"(r[3]) : "r"(addr));
}
__device__ __forceinline__ void cpa16(uint32_t dst, const void* src) {
    asm volatile("cp.async.cg.shared.global [%0], [%1], 16;" :: "r"(dst), "l"(src));
}
__device__ __forceinline__ void cpa_commit() {
    asm volatile("cp.async.commit_group;" ::: "memory");
}
template <int N>
__device__ __forceinline__ void cpa_wait() {
    asm volatile("cp.async.wait_group %0;" :: "n"(N) : "memory");
}

// ---------------------------------------------------------------------------
__global__ void __launch_bounds__(256)
stats_partial(const float* __restrict__ x, int S) {
    const int b = blockIdx.x, c = blockIdx.y;
    const int chunk = (S + NCHUNK - 1) / NCHUNK;
    const int s0 = c * chunk;
    const int s1 = min(s0 + chunk, S);
    const float* xb = x + (size_t)b * S + s0;
    const int n = s1 - s0;

    float sum = 0.f, sq = 0.f;
    int pre = (int)(((16u - (unsigned)((size_t)xb & 15u)) & 15u) >> 2);
    if (pre > n) pre = n;
    for (int i = threadIdx.x; i < pre; i += 256) { float v = xb[i]; sum += v; sq += v*v; }
    int n4 = (n - pre) >> 2;
    const float4* x4 = (const float4*)(xb + pre);
    for (int i = threadIdx.x; i < n4; i += 256) {
        float4 v = x4[i];
        sum += v.x + v.y + v.z + v.w;
        sq  += v.x*v.x + v.y*v.y + v.z*v.z + v.w*v.w;
    }
    for (int i = pre + (n4 << 2) + threadIdx.x; i < n; i += 256) { float v = xb[i]; sum += v; sq += v*v; }

    __shared__ float ssum[8], ssq[8];
    #pragma unroll
    for (int o = 16; o > 0; o >>= 1) {
        sum += __shfl_xor_sync(~0u, sum, o);
        sq  += __shfl_xor_sync(~0u, sq,  o);
    }
    int w = threadIdx.x >> 5, ln = threadIdx.x & 31;
    if (ln == 0) { ssum[w] = sum; ssq[w] = sq; }
    __syncthreads();
    if (w == 0 && ln < 8) {
        sum = ssum[ln]; sq = ssq[ln];
        #pragma unroll
        for (int o = 4; o > 0; o >>= 1) {
            sum += __shfl_xor_sync(0xffu, sum, o);
            sq  += __shfl_xor_sync(0xffu, sq,  o);
        }
        if (ln == 0) { g_psum[b*NCHUNK+c] = sum; g_psq[b*NCHUNK+c] = sq; }
    }
}

__global__ void stats_final(int S) {
    int b = threadIdx.x;
    if (b >= NB) return;
    float sum = 0.f, sq = 0.f;
    #pragma unroll
    for (int c = 0; c < NCHUNK; c++) { sum += g_psum[b*NCHUNK+c]; sq += g_psq[b*NCHUNK+c]; }
    float mu  = sum / (float)S;
    float var = sq / (float)S - mu * mu;
    g_mu[b] = mu;
    g_sd[b] = sqrtf(fmaxf(var, 0.f));
}

// ---------------------------------------------------------------------------
__global__ void prep_b_kernel(const float* __restrict__ kr,
                              const float* __restrict__ ki) {
    int idx = blockIdx.x * blockDim.x + threadIdx.x;
    if (idx >= NCHK * 256 * BP) return;
    int kk = idx % BP;
    int n  = (idx / BP) & 255;
    int c  = idx / (256 * BP);
    int k  = c * KC + kk;
    float v = 0.f;
    if (kk < KC && k < LEN)
        v = ((n < NH) ? kr : ki)[(size_t)(n & 127) * LEN + k];
    __half h = __float2half_rn(v);
    g_bh[idx] = h;
    g_bl[idx] = __float2half_rn(v - __half2float(h));
}

// ---------------------------------------------------------------------------
// Fused: frame+normalize (fp16 hi/lo) + 3xFP16 HMMA DFT
// ldmatrix fragments + cp.async double-buffered B.
// grid (T/128, NB), 512 threads = 16 warps (4m x 4n); warp tile 32t x 64n.
// ---------------------------------------------------------------------------
__global__ void __launch_bounds__(512, 1)
dft_mma_kernel(const float* __restrict__ x,
               float* __restrict__ out, int S, int T) {
    extern __shared__ char smem[];
    const uint32_t smb = (uint32_t)__cvta_generic_to_shared(smem);

    const int tid  = threadIdx.x;
    const int lane = tid & 31;
    const int wid  = tid >> 5;
    const int g    = lane >> 2;
    const int q    = lane & 3;
    const int wm   = wid & 3;
    const int wn   = wid >> 2;
    const int tw   = wm * 32;
    const int nw   = wn * 64;

    const int b  = blockIdx.y;
    const int t0 = blockIdx.x * MTILE;
    const float mu  = g_mu[b];
    const float inv = 1.f / (g_sd[b] + EPSF);
    const float* xrow = x + (size_t)b * S + (size_t)t0 * SHIFT;

    // kick off B chunk 0 streaming while we stage frames
    {
        const char* sH = (const char*)(g_bh);
        const char* sL = (const char*)(g_bl);
        for (int i = tid * 16; i < BCH; i += NTHR * 16) {
            cpa16(smb + SM_B0H + i, sH + i);
            cpa16(smb + SM_B0L + i, sL + i);
        }
        cpa_commit();
    }

    // stage frames: [t][k] normalized, hi/lo split
    {
        uint32_t* fh = (uint32_t*)(smem + SM_FH);
        uint32_t* fl = (uint32_t*)(smem + SM_FL);
        for (int i = tid; i < MTILE * (FP / 2); i += NTHR) {
            const int t  = i / (FP / 2);
            const int kp = (i % (FP / 2)) * 2;
            const float* src = xrow + t * SHIFT + kp;
            float v0 = (src[0] - mu) * inv;
            float v1 = (src[1] - mu) * inv;
            __half h0 = __float2half_rn(v0), h1 = __float2half_rn(v1);
            __half l0 = __float2half_rn(v0 - __half2float(h0));
            __half l1 = __float2half_rn(v1 - __half2float(h1));
            fh[i] = (uint32_t)__half_as_ushort(h0) | ((uint32_t)__half_as_ushort(h1) << 16);
            fl[i] = (uint32_t)__half_as_ushort(l0) | ((uint32_t)__half_as_ushort(l1) << 16);
        }
    }

    float acc[2][8][4];
    #pragma unroll
    for (int mt = 0; mt < 2; mt++)
        #pragma unroll
        for (int nt = 0; nt < 8; nt++)
            #pragma unroll
            for (int i = 0; i < 4; i++) acc[mt][nt][i] = 0.f;

    // per-lane ldmatrix bases
    const uint32_t aAh = smb + SM_FH +
        (uint32_t)(((tw + (lane & 15)) * FP + ((lane >> 4) << 3)) * 2);
    const uint32_t aAl = aAh + (SM_FL - SM_FH);
    const uint32_t bOff =
        (uint32_t)((((lane & 7) + ((lane >> 4) << 3)) * BP + ((lane >> 3) & 1) * 8) * 2);

    for (int c = 0; c < NCHK; c++) {
        // stream next chunk into the other buffer
        if (c < NCHK - 1) {
            const char* sH = (const char*)(g_bh + (c + 1) * 256 * BP);
            const char* sL = (const char*)(g_bl + (c + 1) * 256 * BP);
            const uint32_t dH = smb + (((c + 1) & 1) ? SM_B1H : SM_B0H);
            const uint32_t dL = smb + (((c + 1) & 1) ? SM_B1L : SM_B0L);
            for (int i = tid * 16; i < BCH; i += NTHR * 16) {
                cpa16(dH + i, sH + i);
                cpa16(dL + i, sL + i);
            }
            cpa_commit();
            cpa_wait<1>();     // chunk c landed
        } else {
            cpa_wait<0>();
        }
        __syncthreads();

        const uint32_t aBh = smb + ((c & 1) ? SM_B1H : SM_B0H) + bOff;
        const uint32_t aBl = smb + ((c & 1) ? SM_B1L : SM_B0L) + bOff;
        const int nsteps = (c < 4) ? 3 : 1;

        #pragma unroll
        for (int ks = 0; ks < 3; ks++) {
            if (ks >= nsteps) break;
            const uint32_t kgb = (uint32_t)((c * KC + ks * 16) * 2);  // A k offset, bytes
            const uint32_t klb = (uint32_t)((ks * 16) * 2);           // B local k offset

            uint32_t ah[2][4], al[2][4];
            ldsm4(ah[0], aAh + kgb);
            ldsm4(ah[1], aAh + kgb + 16 * FP * 2);
            ldsm4(al[0], aAl + kgb);
            ldsm4(al[1], aAl + kgb + 16 * FP * 2);

            #pragma unroll
            for (int h = 0; h < 2; h++) {
                uint32_t bh4[2][4], bl4[2][4];
                #pragma unroll
                for (int p = 0; p < 2; p++) {
                    const uint32_t noff = (uint32_t)((nw + (h * 4 + p * 2) * 8) * BP * 2);
                    ldsm4(bh4[p], aBh + noff + klb);
                    ldsm4(bl4[p], aBl + noff + klb);
                }
                uint32_t bhf[4][2], blf[4][2];
                #pragma unroll
                for (int u = 0; u < 4; u++) {
                    bhf[u][0] = bh4[u >> 1][(u & 1) * 2];
                    bhf[u][1] = bh4[u >> 1][(u & 1) * 2 + 1];
                    blf[u][0] = bl4[u >> 1][(u & 1) * 2];
                    blf[u][1] = bl4[u >> 1][(u & 1) * 2 + 1];
                }
                #pragma unroll
                for (int u = 0; u < 4; u++) {
                    mma16(acc[0][h * 4 + u], ah[0], bhf[u]);
                    mma16(acc[1][h * 4 + u], ah[1], bhf[u]);
                }
                #pragma unroll
                for (int u = 0; u < 4; u++) {
                    mma16(acc[0][h * 4 + u], al[0], bhf[u]);
                    mma16(acc[1][h * 4 + u], al[1], bhf[u]);
                }
                #pragma unroll
                for (int u = 0; u < 4; u++) {
                    mma16(acc[0][h * 4 + u], ah[0], blf[u]);
                    mma16(acc[1][h * 4 + u], ah[1], blf[u]);
                }
            }
        }
        __syncthreads();
    }

    // ---- epilogue (pitch 132) ----
    float* imst = (float*)(smem + OFF_IM);
    float* vst  = (float*)(smem + OFF_V);
    float* mn   = (float*)(smem + OFF_MEAN);
    float* ivn  = (float*)(smem + OFF_INV);

    if (wn >= 2) {   // stage imaginary part (cols 128..255)
        #pragma unroll
        for (int mt = 0; mt < 2; mt++)
            #pragma unroll
            for (int nt = 0; nt < 8; nt++) {
                const int ni = (wn - 2) * 64 + nt * 8 + 2 * q;
                const int t  = tw + mt * 16 + g;
                imst[ni * 132 + t]           = acc[mt][nt][0];
                imst[(ni + 1) * 132 + t]     = acc[mt][nt][1];
                imst[ni * 132 + t + 8]       = acc[mt][nt][2];
                imst[(ni + 1) * 132 + t + 8] = acc[mt][nt][3];
            }
    }
    __syncthreads();
    if (wn < 2) {    // combine with real part -> v = log10(mag)
        #pragma unroll
        for (int mt = 0; mt < 2; mt++)
            #pragma unroll
            for (int nt = 0; nt < 8; nt++) {
                const int n = nw + nt * 8 + 2 * q;
                const int t = tw + mt * 16 + g;
                #pragma unroll
                for (int e = 0; e < 4; e++) {
                    const int nn = n + (e & 1);
                    const int tt = t + ((e >> 1) << 3);
                    float re = acc[mt][nt][e];
                    float im = imst[nn * 132 + tt];
                    float m2 = fmaxf(re * re + im * im, 1e-14f);
                    vst[nn * 132 + tt] = __logf(m2) * HALF_INV_LN10;
                }
            }
    }
    __syncthreads();
    if (tid < MTILE) {
        const int t = tid;
        float sum = 0.f, sq = 0.f;
        #pragma unroll 8
        for (int n = 0; n < NH; n++) {
            float v = vst[n * 132 + t];
            sum += v; sq += v * v;
        }
        const float mean = sum * (1.f / NH);
        const float var  = sq * (1.f / NH) - mean * mean;
        mn[t]  = mean;
        ivn[t] = 1.f / (sqrtf(fmaxf(var, 0.f)) + EPSF);
    }
    __syncthreads();
    for (int idx = tid; idx < NH * MTILE; idx += NTHR) {
        const int n = idx >> 7, t = idx & 127;
        out[((size_t)(b * NH + n)) * T + t0 + t] = (vst[n * 132 + t] - mn[t]) * ivn[t];
    }
}

// ---------------------------------------------------------------------------
extern "C" void kernel_launch(void* const* d_in, const int* in_sizes, int n_in,
                              void* d_out, int out_size) {
    const float* x  = (const float*)d_in[0];
    const float* kr = (const float*)d_in[1];
    const float* ki = (const float*)d_in[2];
    float* out = (float*)d_out;

    const int S = in_sizes[0] / NB;            // 480050
    const int T = (S - LEN) / SHIFT + 1;       // 3200

    cudaFuncSetAttribute(dft_mma_kernel, cudaFuncAttributeMaxDynamicSharedMemorySize, SMEM_TOTAL);

    stats_partial<<<dim3(NB, NCHUNK), 256>>>(x, S);
    stats_final<<<1, 64>>>(S);
    prep_b_kernel<<<(NCHK * 256 * BP + 255) / 256, 256>>>(kr, ki);
    dft_mma_kernel<<<dim3(T / MTILE, NB), 512, SMEM_TOTAL>>>(x, out, S, T);
}